// round 4
// baseline (speedup 1.0000x reference)
#include <cuda_runtime.h>
#include <cstdint>

// Problem constants: G=512, GP=256, keys fit in 24 bits since b==0.
#define NKEYS  (1u << 24)          // 16,777,216 possible parent keys
#define NWORDS (1u << 19)          // bitmap words (32 keys/word) = 524,288
#define NBLKS  (NWORDS / 1024)     // 512 scan blocks
#define NMAX   4000000

// Scratch (static device globals — no allocation allowed in kernel_launch)
__device__ unsigned int g_bitmap[NWORDS];     // presence bitmap over key space
__device__ unsigned int g_wprefix[NWORDS];    // per-word exclusive popcount prefix (within block)
__device__ unsigned int g_blocksums[NBLKS];   // per-block totals -> exclusive prefix
__device__ unsigned int g_total;              // total number of unique keys
__device__ unsigned int g_combined[NMAX];     // (key<<3)|offset per point

// ---------------------------------------------------------------------------
// Zero the feats region of d_out: [N*4, N*4 + N*8) floats == 2N float4.
// ---------------------------------------------------------------------------
__global__ void k_zero_feats(float4* __restrict__ feats4, int n2) {
    int i = blockIdx.x * blockDim.x + threadIdx.x;
    if (i < n2) feats4[i] = make_float4(0.f, 0.f, 0.f, 0.f);
}

__global__ void k_zero_bitmap() {
    unsigned i = blockIdx.x * blockDim.x + threadIdx.x;
    if (i < NWORDS / 4) reinterpret_cast<uint4*>(g_bitmap)[i] = make_uint4(0, 0, 0, 0);
}

// ---------------------------------------------------------------------------
// Pass 1: per point, compute key + child-offset, mark presence bit.
// coords row = {b, x, y, z}; parent = xyz>>1; offset = (x&1)*4+(y&1)*2+(z&1)
// key = ((b*256 + px)*256 + py)*256 + pz   (< 2^24 since b==0)
// ---------------------------------------------------------------------------
__global__ void k_build(const int4* __restrict__ coords, int n) {
    int i = blockIdx.x * blockDim.x + threadIdx.x;
    if (i >= n) return;
    int4 c = coords[i];
    unsigned b  = (unsigned)c.x;
    unsigned px = ((unsigned)c.y) >> 1;
    unsigned py = ((unsigned)c.z) >> 1;
    unsigned pz = ((unsigned)c.w) >> 1;
    unsigned off = (((unsigned)c.y & 1u) << 2) | (((unsigned)c.z & 1u) << 1) | ((unsigned)c.w & 1u);
    unsigned key = ((b * 256u + px) * 256u + py) * 256u + pz;
    g_combined[i] = (key << 3) | off;
    atomicOr(&g_bitmap[key >> 5], 1u << (key & 31u));
}

// ---------------------------------------------------------------------------
// Pass 2a: per-block (1024 words) exclusive scan of popcounts.
// ---------------------------------------------------------------------------
__global__ void k_scan_words() {
    __shared__ unsigned warp_sums[32];
    unsigned w = blockIdx.x * 1024u + threadIdx.x;
    unsigned c = __popc(g_bitmap[w]);

    unsigned v = c;  // warp inclusive scan
    #pragma unroll
    for (int d = 1; d < 32; d <<= 1) {
        unsigned t = __shfl_up_sync(0xFFFFFFFFu, v, d);
        if ((threadIdx.x & 31u) >= (unsigned)d) v += t;
    }
    if ((threadIdx.x & 31u) == 31u) warp_sums[threadIdx.x >> 5] = v;
    __syncthreads();
    if (threadIdx.x < 32) {
        unsigned s = warp_sums[threadIdx.x];
        #pragma unroll
        for (int d = 1; d < 32; d <<= 1) {
            unsigned t = __shfl_up_sync(0xFFFFFFFFu, s, d);
            if (threadIdx.x >= (unsigned)d) s += t;
        }
        warp_sums[threadIdx.x] = s;  // inclusive warp totals
    }
    __syncthreads();
    unsigned warp_off = (threadIdx.x >= 32) ? warp_sums[(threadIdx.x >> 5) - 1] : 0u;
    g_wprefix[w] = warp_off + v - c;                 // exclusive within block
    if (threadIdx.x == 1023) g_blocksums[blockIdx.x] = warp_off + v;  // block total
}

// ---------------------------------------------------------------------------
// Pass 2b: exclusive scan of 512 block totals (one block); publish g_total.
// ---------------------------------------------------------------------------
__global__ void k_scan_blocks() {
    __shared__ unsigned warp_sums[16];
    unsigned c = g_blocksums[threadIdx.x];
    unsigned v = c;
    #pragma unroll
    for (int d = 1; d < 32; d <<= 1) {
        unsigned t = __shfl_up_sync(0xFFFFFFFFu, v, d);
        if ((threadIdx.x & 31u) >= (unsigned)d) v += t;
    }
    if ((threadIdx.x & 31u) == 31u) warp_sums[threadIdx.x >> 5] = v;
    __syncthreads();
    if (threadIdx.x < 16) {
        unsigned s = warp_sums[threadIdx.x];
        #pragma unroll
        for (int d = 1; d < 16; d <<= 1) {
            unsigned t = __shfl_up_sync(0xFFFFu, s, d);
            if (threadIdx.x >= (unsigned)d) s += t;
        }
        warp_sums[threadIdx.x] = s;
    }
    __syncthreads();
    unsigned warp_off = (threadIdx.x >= 32) ? warp_sums[(threadIdx.x >> 5) - 1] : 0u;
    g_blocksums[threadIdx.x] = warp_off + v - c;     // exclusive block prefix
    if (threadIdx.x == NBLKS - 1) g_total = warp_off + v;
}

// ---------------------------------------------------------------------------
// Pass 3: per point, rank = prefix + popc(lower bits), atomic add feature.
// ---------------------------------------------------------------------------
__global__ void k_scatter(const float* __restrict__ feats, float* __restrict__ out_feats, int n) {
    int i = blockIdx.x * blockDim.x + threadIdx.x;
    if (i >= n) return;
    unsigned comb = g_combined[i];
    unsigned key  = comb >> 3;
    unsigned off  = comb & 7u;
    unsigned w    = key >> 5;
    unsigned bit  = key & 31u;
    unsigned word = g_bitmap[w];
    unsigned rank = g_wprefix[w] + g_blocksums[w >> 10]
                  + (unsigned)__popc(word & ((1u << bit) - 1u));
    atomicAdd(&out_feats[(size_t)rank * 8u + off], feats[i]);
}

// ---------------------------------------------------------------------------
// Pass 4a: emit sorted unique coords AS FLOAT32 (single-output-dtype harness:
// int -1 bit pattern reads back as NaN float -> must store float values).
// ---------------------------------------------------------------------------
__global__ void k_coords(float4* __restrict__ out_coords) {
    unsigned k = blockIdx.x * blockDim.x + threadIdx.x;
    unsigned w    = k >> 5;
    unsigned bit  = k & 31u;
    unsigned word = g_bitmap[w];
    if (!((word >> bit) & 1u)) return;
    unsigned rank = g_wprefix[w] + g_blocksums[w >> 10]
                  + (unsigned)__popc(word & ((1u << bit) - 1u));
    out_coords[rank] = make_float4((float)(k >> 24),
                                   (float)((k >> 16) & 255u),
                                   (float)((k >> 8)  & 255u),
                                   (float)(k & 255u));
}

// ---------------------------------------------------------------------------
// Pass 4b: fill invalid coord rows (rank >= g_total) with -1.0f.
// ---------------------------------------------------------------------------
__global__ void k_fill_invalid(float4* __restrict__ out_coords, int n) {
    int i = blockIdx.x * blockDim.x + threadIdx.x;
    if (i >= n) return;
    if ((unsigned)i >= g_total) out_coords[i] = make_float4(-1.f, -1.f, -1.f, -1.f);
}

extern "C" void kernel_launch(void* const* d_in, const int* in_sizes, int n_in,
                              void* d_out, int out_size) {
    const int4*  coords = (const int4*)d_in[0];
    const float* feats  = (const float*)d_in[1];
    int n = in_sizes[0] / 4;   // N points

    float4* out_coords = (float4*)d_out;
    float*  out_feats  = (float*)((char*)d_out + (size_t)n * 4 * sizeof(float));
    float4* feats4     = (float4*)out_feats;

    int n2 = n * 2;  // feats region in float4s
    k_zero_feats  <<<(n2 + 255) / 256, 256>>>(feats4, n2);
    k_zero_bitmap <<<((NWORDS / 4) + 255) / 256, 256>>>();
    k_build       <<<(n + 255) / 256, 256>>>(coords, n);
    k_scan_words  <<<NBLKS, 1024>>>();
    k_scan_blocks <<<1, NBLKS>>>();
    k_scatter     <<<(n + 255) / 256, 256>>>(feats, out_feats, n);
    k_coords      <<<NKEYS / 256, 256>>>(out_coords);
    k_fill_invalid<<<(n + 255) / 256, 256>>>(out_coords, n);
}